// round 1
// baseline (speedup 1.0000x reference)
#include <cuda_runtime.h>
#include <cstdint>

// Problem constants
#define D_IN   256
#define D_OUT  256
#define BATCH  512
#define KNOTS  64
// H = 4/63, 1/H = 15.75 (exact in fp32)
#define INV_H  15.75f
#define H_VAL  (4.0f/63.0f)

#define NCHUNK 16            // din chunks
#define DCHUNK 16            // din per chunk
#define TILE   (64*65)       // padded smem tile (64 dout rows x 65 floats)
#define SMEM_FLOATS (4*TILE + 4096*4 + 4096)   // 2x dbl-buffered y/hm + weights(float4) + idx
#define SMEM_BYTES  (SMEM_FLOATS * 4)

// Scratch (device globals; no allocation)
__device__ float g_hm[(size_t)D_IN * D_OUT * KNOTS];          // 16 MB: H * pchip slopes
__device__ float g_partial[(size_t)NCHUNK * BATCH * D_OUT];   // 8 MB: per-chunk partials

// ---------------------------------------------------------------------------
// Kernel A: PCHIP slopes.  One thread per spline (din,dout), smem-staged I/O.
// ---------------------------------------------------------------------------
__global__ void __launch_bounds__(128) pchip_kernel(const float* __restrict__ y) {
    __shared__ float s[128][65];
    const int t = threadIdx.x;
    const size_t base = (size_t)blockIdx.x * 128 * KNOTS;
    const float* src = y + base;

    // coalesced load of 128 splines x 64 knots
    for (int j = t; j < 128 * 64; j += 128) s[j >> 6][j & 63] = src[j];
    __syncthreads();

    float* row = s[t];   // this thread's spline (bank-conflict-free: stride 65)

    float y0 = row[0], y1 = row[1], y2 = row[2];
    float dprev = (y1 - y0) * INV_H;   // delta0
    float dcur  = (y2 - y1) * INV_H;   // delta1

    // left endpoint m0
    float m0 = (3.0f * dprev - dcur) * 0.5f;
    if (m0 * dprev <= 0.0f) m0 = 0.0f;
    else if (dprev * dcur < 0.0f && fabsf(m0) > 3.0f * fabsf(dprev)) m0 = 3.0f * dprev;
    row[0] = H_VAL * m0;

    float yc = y2;  // y[j+1] for current j
    for (int j = 1; j <= 62; ++j) {
        // interior m_j from dprev = delta[j-1], dcur = delta[j]
        float m = 0.0f;
        if (dprev * dcur > 0.0f) {
            float denom = dprev + dcur;
            m = (fabsf(denom) < 1e-12f) ? 0.0f
                                        : __fdividef(2.0f * dprev * dcur, denom);
        }
        row[j] = H_VAL * m;           // overwrites y[j]; deltas already consumed it
        if (j < 62) {
            float yn = row[j + 2];    // original y[j+2] (untouched)
            float dnext = (yn - yc) * INV_H;
            dprev = dcur; dcur = dnext; yc = yn;
        }
    }
    // right endpoint m63 from dprev = delta61, dcur = delta62
    float mN = (3.0f * dcur - dprev) * 0.5f;
    if (mN * dcur <= 0.0f) mN = 0.0f;
    else if (dcur * dprev < 0.0f && fabsf(mN) > 3.0f * fabsf(dcur)) mN = 3.0f * dcur;
    row[63] = H_VAL * mN;

    __syncthreads();
    float* dst = g_hm + base;
    for (int j = t; j < 128 * 64; j += 128) dst[j] = s[j >> 6][j & 63];
}

// ---------------------------------------------------------------------------
// Kernel B: main gather-accumulate.
// Grid: (4 dout tiles, 2 b tiles, 16 din chunks). Block: 256 threads.
// Warp w owns b rows [w*32, w*32+32); lane l owns dout l and l+32 (local).
// ---------------------------------------------------------------------------
__device__ __forceinline__ void cp_async4(float* dst, const float* src) {
    unsigned sa = (unsigned)__cvta_generic_to_shared(dst);
    asm volatile("cp.async.ca.shared.global [%0], [%1], 4;\n" :: "r"(sa), "l"(src));
}

__global__ void __launch_bounds__(256, 1) kan_main_kernel(
        const float* __restrict__ x, const float* __restrict__ y) {
    extern __shared__ float sm[];
    float* sw_f  = sm + 4 * TILE;                  // float4[4096] weights
    int*   sidx  = (int*)(sw_f + 4096 * 4);        // int[4096]

    const int dx  = blockIdx.x;   // dout tile (0..3)
    const int by  = blockIdx.y;   // b tile    (0..1)
    const int ch  = blockIdx.z;   // din chunk (0..15)
    const int tid = threadIdx.x;

    // ---- precompute hermite weights for (256 b) x (16 din) ----
    for (int i = tid; i < 256 * DCHUNK; i += 256) {
        int bb = i >> 4;          // b within tile
        int dl = i & 15;          // din within chunk
        int b   = by * 256 + bb;
        int din = ch * DCHUNK + dl;
        float xv = x[b * D_IN + din];
        xv = fminf(fmaxf(xv, -2.0f), 2.0f);
        float tt = (xv + 2.0f) * INV_H;
        int idx = (int)floorf(tt);
        if (idx > KNOTS - 2) idx = KNOTS - 2;
        if (idx < 0) idx = 0;
        float u  = tt - (float)idx;
        float u2 = u * u, u3 = u2 * u;
        float h00 = 2.0f * u3 - 3.0f * u2 + 1.0f;
        float h10 = u3 - 2.0f * u2 + u;
        float h01 = 3.0f * u2 - 2.0f * u3;
        float h11 = u3 - u2;
        ((float4*)sw_f)[i] = make_float4(h00, h01, h10, h11);
        sidx[i] = idx;
    }

    const int w = tid >> 5, l = tid & 31;
    float acc0[32], acc1[32];
#pragma unroll
    for (int bb = 0; bb < 32; ++bb) { acc0[bb] = 0.0f; acc1[bb] = 0.0f; }

    // ---- async tile copy (scalar cp.async: odd-stride padded layout) ----
    auto issue_copy = [&](int d, int st) {
        const size_t srcoff = ((size_t)(ch * DCHUNK + d) * D_OUT + dx * 64) * KNOTS;
        const float* ys = y + srcoff;
        const float* hs = g_hm + srcoff;
        float* yd = sm + st * TILE;
        float* hd = sm + (2 + st) * TILE;
        for (int j = tid; j < 4096; j += 256) {
            int o = (j >> 6) * 65 + (j & 63);
            cp_async4(yd + o, ys + j);
            cp_async4(hd + o, hs + j);
        }
    };

    issue_copy(0, 0);
    asm volatile("cp.async.commit_group;\n" ::: "memory");

    for (int d = 0; d < DCHUNK; ++d) {
        const int st = d & 1;
        if (d < DCHUNK - 1) {
            issue_copy(d + 1, st ^ 1);
            asm volatile("cp.async.commit_group;\n" ::: "memory");
            asm volatile("cp.async.wait_group 1;\n" ::: "memory");
        } else {
            asm volatile("cp.async.wait_group 0;\n" ::: "memory");
        }
        __syncthreads();

        const float* ry = sm + st * TILE + l * 65;        // dout row l
        const float* rh = sm + (2 + st) * TILE + l * 65;
        const float4* swp = (const float4*)sw_f;
        const int base = (w * 32) * DCHUNK + d;

#pragma unroll
        for (int bb = 0; bb < 32; ++bb) {
            float4 wt = swp[base + bb * DCHUNK];          // uniform -> broadcast
            int    i  = sidx[base + bb * DCHUNK];
            // dout = l
            float a  = wt.x * ry[i];
            a += wt.y * ry[i + 1];
            a += wt.z * rh[i];
            a += wt.w * rh[i + 1];
            // dout = l + 32
            float b2 = wt.x * ry[i + 32 * 65];
            b2 += wt.y * ry[i + 1 + 32 * 65];
            b2 += wt.z * rh[i + 32 * 65];
            b2 += wt.w * rh[i + 1 + 32 * 65];
            acc0[bb] += a;
            acc1[bb] += b2;
        }
        __syncthreads();
    }

    // ---- write partials ----
    float* P = g_partial + (((size_t)ch * BATCH + by * 256 + w * 32) * D_OUT) + dx * 64;
#pragma unroll
    for (int bb = 0; bb < 32; ++bb) {
        P[bb * D_OUT + l]      = acc0[bb];
        P[bb * D_OUT + l + 32] = acc1[bb];
    }
}

// ---------------------------------------------------------------------------
// Kernel C: reduce 16 partials + bias
// ---------------------------------------------------------------------------
__global__ void __launch_bounds__(256) reduce_kernel(
        const float* __restrict__ bias, float* __restrict__ out) {
    int i = blockIdx.x * 256 + threadIdx.x;            // float4 index, 0..32767
    const float4* P = (const float4*)g_partial;
    float4 s = ((const float4*)bias)[i & 63];
#pragma unroll
    for (int c = 0; c < NCHUNK; ++c) {
        float4 p = P[(size_t)c * (BATCH * D_OUT / 4) + i];
        s.x += p.x; s.y += p.y; s.z += p.z; s.w += p.w;
    }
    ((float4*)out)[i] = s;
}

// ---------------------------------------------------------------------------
extern "C" void kernel_launch(void* const* d_in, const int* in_sizes, int n_in,
                              void* d_out, int out_size) {
    const float* x    = (const float*)d_in[0];
    const float* y    = (const float*)d_in[1];
    const float* bias = (const float*)d_in[2];
    float* out = (float*)d_out;

    cudaFuncSetAttribute(kan_main_kernel,
                         cudaFuncAttributeMaxDynamicSharedMemorySize, SMEM_BYTES);

    pchip_kernel<<<(D_IN * D_OUT) / 128, 128>>>(y);
    kan_main_kernel<<<dim3(4, 2, 16), 256, SMEM_BYTES>>>(x, y);
    reduce_kernel<<<(BATCH * D_OUT / 4) / 256, 256>>>(bias, out);
}

// round 2
// speedup vs baseline: 1.0581x; 1.0581x over previous
#include <cuda_runtime.h>
#include <cuda_fp16.h>
#include <cstdint>

// Problem constants
#define D_IN   256
#define D_OUT  256
#define BATCH  512
#define KNOTS  64
#define INV_H  15.75f          // 63/4, exact in fp32
#define H_VAL  (4.0f/63.0f)

#define NCHUNK 16              // din chunks
#define DCHUNK 16              // din per chunk
#define TB     128             // batch rows per block

// padded tile: 64 dout rows x 65 half2 slots (4B each)
#define TSTRIDE 65
#define TILE_U  (64*TSTRIDE)   // 4160 words (4B)

// smem word offsets
#define OFF_YP  0
#define OFF_HP  (2*TILE_U)               // 8320
#define OFF_W   (4*TILE_U)               // 16640 (16B aligned: 66560B)
#define OFF_IDX (OFF_W + TB*DCHUNK*4)    // 24832
#define SMEM_WORDS (OFF_IDX + TB*DCHUNK) // 26880
#define SMEM_BYTES (SMEM_WORDS*4)        // 107520

// Scratch (device globals; no allocation)
__device__ __half2 g_yp[(size_t)D_IN * D_OUT * KNOTS];        // 16 MB: (y[j], y[j+1])
__device__ __half2 g_hp[(size_t)D_IN * D_OUT * KNOTS];        // 16 MB: (hm[j], hm[j+1])
__device__ float   g_partial[(size_t)NCHUNK * BATCH * D_OUT]; // 8 MB

// ---------------------------------------------------------------------------
// Kernel A: PCHIP slopes + fp16 pair-packing. Warp per spline, shuffle deltas.
// ---------------------------------------------------------------------------
__device__ __forceinline__ float pchip_interior(float d0, float d1) {
    float m = 0.0f;
    if (d0 * d1 > 0.0f) {
        float den = d0 + d1;
        m = (fabsf(den) < 1e-12f) ? 0.0f : (2.0f * d0 * d1 / den);
    }
    return m;
}

__global__ void __launch_bounds__(256) pchip_pack_kernel(const float* __restrict__ y) {
    const int lane = threadIdx.x & 31;
    const size_t s = (size_t)blockIdx.x * 8 + (threadIdx.x >> 5);   // spline id

    float2 v = ((const float2*)(y + s * KNOTS))[lane];
    float y0 = v.x, y1 = v.y;                                   // y[2l], y[2l+1]
    float y2 = __shfl_down_sync(0xFFFFFFFFu, y0, 1);            // y[2l+2] (lane31 junk)

    float da = (y1 - y0) * INV_H;                               // delta[2l]
    float db = (y2 - y1) * INV_H;                               // delta[2l+1] (lane31 junk)
    float dprev = __shfl_up_sync(0xFFFFFFFFu, db, 1);           // delta[2l-1] (lane0 junk)

    float m_e, m_o;
    if (lane == 0) {                                            // knot 0 endpoint
        float m0 = (3.0f * da - db) * 0.5f;
        if (m0 * da <= 0.0f) m0 = 0.0f;
        else if (da * db < 0.0f && fabsf(m0) > 3.0f * fabsf(da)) m0 = 3.0f * da;
        m_e = m0;
    } else {
        m_e = pchip_interior(dprev, da);                        // knot 2l
    }
    if (lane == 31) {                                           // knot 63 endpoint
        float mN = (3.0f * da - dprev) * 0.5f;                  // delta62=da, delta61=dprev
        if (mN * da <= 0.0f) mN = 0.0f;
        else if (da * dprev < 0.0f && fabsf(mN) > 3.0f * fabsf(da)) mN = 3.0f * da;
        m_o = mN;
    } else {
        m_o = pchip_interior(da, db);                           // knot 2l+1
    }

    float he = H_VAL * m_e, ho = H_VAL * m_o;                   // hm[2l], hm[2l+1]
    float he_next = __shfl_down_sync(0xFFFFFFFFu, he, 1);       // hm[2l+2]

    __half2 yp0 = __floats2half2_rn(y0, y1);
    __half2 yp1 = (lane == 31) ? __floats2half2_rn(0.f, 0.f) : __floats2half2_rn(y1, y2);
    __half2 hp0 = __floats2half2_rn(he, ho);
    __half2 hp1 = (lane == 31) ? __floats2half2_rn(0.f, 0.f) : __floats2half2_rn(ho, he_next);

    uint2 py, ph;
    py.x = *reinterpret_cast<unsigned*>(&yp0); py.y = *reinterpret_cast<unsigned*>(&yp1);
    ph.x = *reinterpret_cast<unsigned*>(&hp0); ph.y = *reinterpret_cast<unsigned*>(&hp1);
    ((uint2*)(g_yp + s * KNOTS))[lane] = py;
    ((uint2*)(g_hp + s * KNOTS))[lane] = ph;
}

// ---------------------------------------------------------------------------
// Kernel B: main gather-accumulate (fp16 tiles, fp32 weights+accum).
// Grid (4 dout tiles, 4 b tiles, 16 din chunks) = 256 blocks, 256 thr.
// Warp w owns b rows [w*16, w*16+16); lane l owns douts l and l+32 (local).
// ---------------------------------------------------------------------------
__device__ __forceinline__ void cp_async4(void* dst, const void* src) {
    unsigned sa = (unsigned)__cvta_generic_to_shared(dst);
    asm volatile("cp.async.ca.shared.global [%0], [%1], 4;\n" :: "r"(sa), "l"(src));
}

__global__ void __launch_bounds__(256, 2) kan_main_kernel(const float* __restrict__ x) {
    extern __shared__ unsigned sm[];
    unsigned* yp  = sm + OFF_YP;
    unsigned* hp  = sm + OFF_HP;
    float4*  wts  = (float4*)(sm + OFF_W);
    int*     sidx = (int*)(sm + OFF_IDX);

    const int dx  = blockIdx.x;   // dout tile (0..3)
    const int by  = blockIdx.y;   // b tile    (0..3)
    const int ch  = blockIdx.z;   // din chunk (0..15)
    const int tid = threadIdx.x;

    // ---- hermite weights for (128 b) x (16 din) ----
    for (int i = tid; i < TB * DCHUNK; i += 256) {
        int bb = i >> 4, dl = i & 15;
        float xv = x[(by * TB + bb) * D_IN + ch * DCHUNK + dl];
        xv = fminf(fmaxf(xv, -2.0f), 2.0f);
        float tt = (xv + 2.0f) * INV_H;
        int idx = (int)floorf(tt);
        if (idx > KNOTS - 2) idx = KNOTS - 2;
        if (idx < 0) idx = 0;
        float u  = tt - (float)idx;
        float u2 = u * u, u3 = u2 * u;
        float h00 = 2.0f * u3 - 3.0f * u2 + 1.0f;
        float h10 = u3 - 2.0f * u2 + u;
        float h01 = 3.0f * u2 - 2.0f * u3;
        float h11 = u3 - u2;
        wts[i]  = make_float4(h00, h01, h10, h11);
        sidx[i] = idx;
    }

    const int w = tid >> 5, l = tid & 31;
    float acc0[16], acc1[16];
#pragma unroll
    for (int bb = 0; bb < 16; ++bb) { acc0[bb] = 0.0f; acc1[bb] = 0.0f; }

    auto issue_copy = [&](int d, int st) {
        size_t g = ((size_t)(ch * DCHUNK + d) * D_OUT + dx * 64) * KNOTS;
        const unsigned* ys = (const unsigned*)g_yp + g;
        const unsigned* hs = (const unsigned*)g_hp + g;
        unsigned* yd = yp + st * TILE_U;
        unsigned* hd = hp + st * TILE_U;
        for (int j = tid; j < 4096; j += 256) {
            int o = (j >> 6) * TSTRIDE + (j & 63);
            cp_async4(yd + o, ys + j);
            cp_async4(hd + o, hs + j);
        }
    };

    issue_copy(0, 0);
    asm volatile("cp.async.commit_group;\n" ::: "memory");

    for (int d = 0; d < DCHUNK; ++d) {
        const int st = d & 1;
        if (d < DCHUNK - 1) {
            issue_copy(d + 1, st ^ 1);
            asm volatile("cp.async.commit_group;\n" ::: "memory");
            asm volatile("cp.async.wait_group 1;\n" ::: "memory");
        } else {
            asm volatile("cp.async.wait_group 0;\n" ::: "memory");
        }
        __syncthreads();

        const unsigned* ry = yp + st * TILE_U + l * TSTRIDE;
        const unsigned* rh = hp + st * TILE_U + l * TSTRIDE;
        const int base = (w * 16) * DCHUNK + d;

#pragma unroll
        for (int bb = 0; bb < 16; ++bb) {
            float4 wt = wts[base + bb * DCHUNK];      // broadcast
            int    i  = sidx[base + bb * DCHUNK];
            __half2 a0 = *(const __half2*)(ry + i);
            __half2 h0 = *(const __half2*)(rh + i);
            __half2 a1 = *(const __half2*)(ry + i + 32 * TSTRIDE);
            __half2 h1 = *(const __half2*)(rh + i + 32 * TSTRIDE);
            float2 fa0 = __half22float2(a0), fh0 = __half22float2(h0);
            float2 fa1 = __half22float2(a1), fh1 = __half22float2(h1);
            acc0[bb] += wt.x * fa0.x + wt.y * fa0.y + wt.z * fh0.x + wt.w * fh0.y;
            acc1[bb] += wt.x * fa1.x + wt.y * fa1.y + wt.z * fh1.x + wt.w * fh1.y;
        }
        __syncthreads();
    }

    // ---- write partials ----
    float* P = g_partial + ((size_t)ch * BATCH + by * TB + w * 16) * D_OUT + dx * 64;
#pragma unroll
    for (int bb = 0; bb < 16; ++bb) {
        P[bb * D_OUT + l]      = acc0[bb];
        P[bb * D_OUT + l + 32] = acc1[bb];
    }
}

// ---------------------------------------------------------------------------
// Kernel C: reduce 16 partials + bias
// ---------------------------------------------------------------------------
__global__ void __launch_bounds__(256) reduce_kernel(
        const float* __restrict__ bias, float* __restrict__ out) {
    int i = blockIdx.x * 256 + threadIdx.x;            // float4 index
    const float4* P = (const float4*)g_partial;
    float4 s = ((const float4*)bias)[i & 63];
#pragma unroll
    for (int c = 0; c < NCHUNK; ++c) {
        float4 p = P[(size_t)c * (BATCH * D_OUT / 4) + i];
        s.x += p.x; s.y += p.y; s.z += p.z; s.w += p.w;
    }
    ((float4*)out)[i] = s;
}

// ---------------------------------------------------------------------------
extern "C" void kernel_launch(void* const* d_in, const int* in_sizes, int n_in,
                              void* d_out, int out_size) {
    const float* x    = (const float*)d_in[0];
    const float* y    = (const float*)d_in[1];
    const float* bias = (const float*)d_in[2];
    float* out = (float*)d_out;

    cudaFuncSetAttribute(kan_main_kernel,
                         cudaFuncAttributeMaxDynamicSharedMemorySize, SMEM_BYTES);

    pchip_pack_kernel<<<(D_IN * D_OUT) / 8, 256>>>(y);
    kan_main_kernel<<<dim3(4, 4, 16), 256, SMEM_BYTES>>>(x);
    reduce_kernel<<<(BATCH * D_OUT / 4) / 256, 256>>>(bias, out);
}

// round 3
// speedup vs baseline: 1.4042x; 1.3271x over previous
#include <cuda_runtime.h>
#include <cuda_fp16.h>
#include <cstdint>

// Problem constants
#define D_IN   256
#define D_OUT  256
#define BATCH  512
#define KNOTS  64
#define INV_H  15.75f          // 63/4, exact in fp32
#define H_VAL  (4.0f/63.0f)

#define NCHUNK 32              // din chunks
#define DCHUNK 8               // din per chunk
#define TB     256             // batch rows per block

// packed tile: 64 dout rows x 65 uint2 slots (8B each), stride 65 => conflict-free LDS.64
#define TSTRIDE 65
#define TILE_U2 (64*TSTRIDE)                 // 4160 uint2

// smem layout (in uint2 units for tiles, then weights)
#define SMEM_TILE_BYTES (2*TILE_U2*8)        // 66560
#define SMEM_W_BYTES    (TB*DCHUNK*8)        // 16384 (uint2 half2-pairs)
#define SMEM_I_BYTES    (TB*DCHUNK*4)        // 8192  (int idx)
#define SMEM_BYTES      (SMEM_TILE_BYTES + SMEM_W_BYTES + SMEM_I_BYTES)  // 91136

// Scratch (device globals; no allocation)
// g_pack[(din*256+dout)*64 + j] = half4 {y_j, y_j+1, hm_j, hm_j+1}  (8B)
__device__ uint2 g_pack[(size_t)D_IN * D_OUT * KNOTS];          // 33.5 MB
__device__ float g_partial[(size_t)NCHUNK * BATCH * D_OUT];     // 16 MB

// ---------------------------------------------------------------------------
// Kernel A: PCHIP slopes + half4 packing. Warp per spline, shuffle deltas,
// branch-free slope math with fast division.
// ---------------------------------------------------------------------------
__device__ __forceinline__ float pchip_interior(float d0, float d1) {
    float p   = d0 * d1;
    float den = d0 + d1;
    float m   = __fdividef(2.0f * p, den);
    bool  ok  = (p > 0.0f) && (fabsf(den) >= 1e-12f);
    return ok ? m : 0.0f;
}

__device__ __forceinline__ float pchip_endpoint(float d_near, float d_far) {
    // m = (3*d_near - d_far)/2, clamped per PCHIP endpoint rules
    float m = 1.5f * d_near - 0.5f * d_far;
    m = (m * d_near <= 0.0f) ? 0.0f : m;
    bool clamp3 = (d_near * d_far < 0.0f) && (fabsf(m) > 3.0f * fabsf(d_near));
    return clamp3 ? 3.0f * d_near : m;
}

__global__ void __launch_bounds__(256) pchip_pack_kernel(const float* __restrict__ y) {
    const int lane = threadIdx.x & 31;
    const size_t s = (size_t)blockIdx.x * 8 + (threadIdx.x >> 5);   // spline id

    float2 v = ((const float2*)(y + s * KNOTS))[lane];
    float y0 = v.x, y1 = v.y;                                   // y[2l], y[2l+1]
    float y2 = __shfl_down_sync(0xFFFFFFFFu, y0, 1);            // y[2l+2] (lane31 junk)

    float da = (y1 - y0) * INV_H;                               // delta[2l]
    float db = (y2 - y1) * INV_H;                               // delta[2l+1] (lane31 junk)
    float dprev = __shfl_up_sync(0xFFFFFFFFu, db, 1);           // delta[2l-1] (lane0 junk)

    // even knot 2l
    float m_e = (lane == 0) ? pchip_endpoint(da, db)            // knot 0
                            : pchip_interior(dprev, da);
    // odd knot 2l+1
    float m_o = (lane == 31) ? pchip_endpoint(da, dprev)        // knot 63 (delta62=da, delta61=dprev)
                             : pchip_interior(da, db);

    float he = H_VAL * m_e, ho = H_VAL * m_o;                   // hm[2l], hm[2l+1]
    float he_next = __shfl_down_sync(0xFFFFFFFFu, he, 1);       // hm[2l+2] (lane31 junk)

    __half2 ya = __floats2half2_rn(y0, y1);
    __half2 ha = __floats2half2_rn(he, ho);
    __half2 yb = __floats2half2_rn(y1, (lane == 31) ? y1 : y2);
    __half2 hb = __floats2half2_rn(ho, (lane == 31) ? ho : he_next);

    uint4 o;
    o.x = *reinterpret_cast<unsigned*>(&ya);
    o.y = *reinterpret_cast<unsigned*>(&ha);
    o.z = *reinterpret_cast<unsigned*>(&yb);
    o.w = *reinterpret_cast<unsigned*>(&hb);
    ((uint4*)(g_pack + s * KNOTS))[lane] = o;                   // pack[2l], pack[2l+1]
}

// ---------------------------------------------------------------------------
// Kernel B: main gather-accumulate.
// Grid (4 dout tiles, 2 b tiles, 32 din chunks) = 256 blocks, 256 threads.
// Warp w owns b rows [w*32, w*32+32); lane l owns douts l and l+32 (local).
// Per (b,din,dout): one LDS.64 (half4) + HMUL2/HFMA2 + fp32 accumulate.
// ---------------------------------------------------------------------------
__device__ __forceinline__ void cp_async8(void* dst, const void* src) {
    unsigned sa = (unsigned)__cvta_generic_to_shared(dst);
    asm volatile("cp.async.ca.shared.global [%0], [%1], 8;\n" :: "r"(sa), "l"(src));
}
__device__ __forceinline__ __half2 u2h(unsigned u) {
    return *reinterpret_cast<__half2*>(&u);
}

__global__ void __launch_bounds__(256, 2) kan_main_kernel(const float* __restrict__ x) {
    extern __shared__ uint2 sm2[];
    uint2* tile = sm2;                               // 2 x TILE_U2
    uint2* wts  = sm2 + 2 * TILE_U2;                 // TB*DCHUNK half2-pairs
    int*   offs = (int*)(wts + TB * DCHUNK);         // TB*DCHUNK

    const int dx  = blockIdx.x;   // dout tile (0..3)
    const int by  = blockIdx.y;   // b tile    (0..1)
    const int ch  = blockIdx.z;   // din chunk (0..31)
    const int tid = threadIdx.x;

    // ---- hermite weights for (256 b) x (8 din), pre-converted to half2 ----
    for (int i = tid; i < TB * DCHUNK; i += 256) {
        int bb = i >> 3, dl = i & 7;
        float xv = x[(by * TB + bb) * D_IN + ch * DCHUNK + dl];
        xv = fminf(fmaxf(xv, -2.0f), 2.0f);
        float tt = (xv + 2.0f) * INV_H;
        int idx = (int)floorf(tt);
        if (idx > KNOTS - 2) idx = KNOTS - 2;
        if (idx < 0) idx = 0;
        float u  = tt - (float)idx;
        float u2 = u * u, u3 = u2 * u;
        float h00 = 2.0f * u3 - 3.0f * u2 + 1.0f;
        float h10 = u3 - 2.0f * u2 + u;
        float h01 = 3.0f * u2 - 2.0f * u3;
        float h11 = u3 - u2;
        __half2 wy = __floats2half2_rn(h00, h01);
        __half2 wh = __floats2half2_rn(h10, h11);
        uint2 wp;
        wp.x = *reinterpret_cast<unsigned*>(&wy);
        wp.y = *reinterpret_cast<unsigned*>(&wh);
        wts[i]  = wp;
        offs[i] = idx;
    }

    const int w = tid >> 5, l = tid & 31;
    float acc0[32], acc1[32];
#pragma unroll
    for (int bb = 0; bb < 32; ++bb) { acc0[bb] = 0.0f; acc1[bb] = 0.0f; }

    auto issue_copy = [&](int d, int st) {
        const uint2* src = g_pack + ((size_t)(ch * DCHUNK + d) * D_OUT + dx * 64) * KNOTS;
        uint2* dst = tile + st * TILE_U2;
        for (int j = tid; j < 4096; j += 256) {
            int o = (j >> 6) * TSTRIDE + (j & 63);
            cp_async8(dst + o, src + j);
        }
    };

    issue_copy(0, 0);
    asm volatile("cp.async.commit_group;\n" ::: "memory");

    for (int d = 0; d < DCHUNK; ++d) {
        const int st = d & 1;
        if (d < DCHUNK - 1) {
            issue_copy(d + 1, st ^ 1);
            asm volatile("cp.async.commit_group;\n" ::: "memory");
            asm volatile("cp.async.wait_group 1;\n" ::: "memory");
        } else {
            asm volatile("cp.async.wait_group 0;\n" ::: "memory");
        }
        __syncthreads();

        const uint2* ry = tile + st * TILE_U2 + l * TSTRIDE;   // dout l
        const uint2* rz = ry + 32 * TSTRIDE;                   // dout l+32
        const int base = (w * 32) * DCHUNK + d;

#pragma unroll
        for (int bb = 0; bb < 32; ++bb) {
            int   i  = offs[base + bb * DCHUNK];               // broadcast
            uint2 wp = wts [base + bb * DCHUNK];               // broadcast
            __half2 wy = u2h(wp.x), wh = u2h(wp.y);

            uint2 g0 = ry[i];
            uint2 g1 = rz[i];

            __half2 p0 = __hfma2(wh, u2h(g0.y), __hmul2(wy, u2h(g0.x)));
            __half2 p1 = __hfma2(wh, u2h(g1.y), __hmul2(wy, u2h(g1.x)));

            acc0[bb] += __half2float(__hadd(__low2half(p0), __high2half(p0)));
            acc1[bb] += __half2float(__hadd(__low2half(p1), __high2half(p1)));
        }
        __syncthreads();
    }

    // ---- write partials ----
    float* P = g_partial + ((size_t)ch * BATCH + by * TB + w * 32) * D_OUT + dx * 64;
#pragma unroll
    for (int bb = 0; bb < 32; ++bb) {
        P[bb * D_OUT + l]      = acc0[bb];
        P[bb * D_OUT + l + 32] = acc1[bb];
    }
}

// ---------------------------------------------------------------------------
// Kernel C: reduce 32 partials + bias
// ---------------------------------------------------------------------------
__global__ void __launch_bounds__(256) reduce_kernel(
        const float* __restrict__ bias, float* __restrict__ out) {
    int i = blockIdx.x * 256 + threadIdx.x;            // float4 index
    const float4* P = (const float4*)g_partial;
    float4 s = ((const float4*)bias)[i & 63];
#pragma unroll
    for (int c = 0; c < NCHUNK; ++c) {
        float4 p = P[(size_t)c * (BATCH * D_OUT / 4) + i];
        s.x += p.x; s.y += p.y; s.z += p.z; s.w += p.w;
    }
    ((float4*)out)[i] = s;
}

// ---------------------------------------------------------------------------
extern "C" void kernel_launch(void* const* d_in, const int* in_sizes, int n_in,
                              void* d_out, int out_size) {
    const float* x    = (const float*)d_in[0];
    const float* y    = (const float*)d_in[1];
    const float* bias = (const float*)d_in[2];
    float* out = (float*)d_out;

    cudaFuncSetAttribute(kan_main_kernel,
                         cudaFuncAttributeMaxDynamicSharedMemorySize, SMEM_BYTES);

    pchip_pack_kernel<<<(D_IN * D_OUT) / 8, 256>>>(y);
    kan_main_kernel<<<dim3(4, 2, NCHUNK), 256, SMEM_BYTES>>>(x);
    reduce_kernel<<<(BATCH * D_OUT / 4) / 256, 256>>>(bias, out);
}